// round 1
// baseline (speedup 1.0000x reference)
#include <cuda_runtime.h>
#include <cuda_bf16.h>

#define GRAPHS 4096
#define NPG 18
#define NNODES (GRAPHS * NPG)
#define FIN 1536
#define EPERG 306   // 18*17 directed edges per graph
#define SLOPE 0.01f
#define BN_EPS 1e-5f

// Scratch: layer-1 projection P1 = X @ W1   [73728, 32]
__device__ float g_P1[(size_t)NNODES * 32];

// ---------------------------------------------------------------------------
// Kernel 1: P1 = X @ W1.  Tile 128 rows x 32 cols, K-tiles of 32.
// 256 threads, each computes 8 rows x 2 cols.
// ---------------------------------------------------------------------------
__global__ __launch_bounds__(256) void gemm1_kernel(
    const float* __restrict__ X, const float* __restrict__ W1)
{
    __shared__ float xs[128][36];   // padded stride to avoid STS conflicts
    __shared__ float ws[32][32];

    const int tid = threadIdx.x;
    const int row0 = blockIdx.x * 128;
    const int tr = tid >> 4;        // 0..15
    const int tc = tid & 15;        // 0..15
    const int r0 = tr * 8;
    const int c0 = tc * 2;

    float acc[8][2];
#pragma unroll
    for (int i = 0; i < 8; i++) { acc[i][0] = 0.f; acc[i][1] = 0.f; }

    for (int k0 = 0; k0 < FIN; k0 += 32) {
        // load X tile: 128 rows x 32 cols = 1024 float4 quarters -> 4/thread
#pragma unroll
        for (int j = 0; j < 4; j++) {
            int idx = tid + j * 256;
            int r = idx >> 3, c4 = idx & 7;
            float4 v = *(const float4*)(X + (size_t)(row0 + r) * FIN + k0 + c4 * 4);
            *(float4*)(&xs[r][c4 * 4]) = v;
        }
        // load W tile: 32x32
#pragma unroll
        for (int j = 0; j < 4; j++) {
            int idx = tid + j * 256;
            ws[idx >> 5][idx & 31] = W1[(size_t)(k0 + (idx >> 5)) * 32 + (idx & 31)];
        }
        __syncthreads();

#pragma unroll
        for (int k = 0; k < 32; k++) {
            float2 w = *(float2*)&ws[k][c0];
#pragma unroll
            for (int i = 0; i < 8; i++) {
                float xv = xs[r0 + i][k];
                acc[i][0] += xv * w.x;
                acc[i][1] += xv * w.y;
            }
        }
        __syncthreads();
    }

#pragma unroll
    for (int i = 0; i < 8; i++) {
        int row = row0 + r0 + i;
        *(float2*)(g_P1 + (size_t)row * 32 + c0) = make_float2(acc[i][0], acc[i][1]);
    }
}

// ---------------------------------------------------------------------------
// Kernel 2: everything else, one CTA per graph (4096 CTAs, 256 threads).
// Builds normalized 18x18 adjacency, then agg1+BN+lrelu, GEMM2, agg2+BN+lrelu,
// GEMM3, agg3+BN+lrelu, mean-pool, 4-layer MLP head.
// ---------------------------------------------------------------------------
__device__ __forceinline__ float lrelu(float v) { return v >= 0.f ? v : SLOPE * v; }

__global__ __launch_bounds__(256) void graph_kernel(
    const float* __restrict__ ew,
    const float* __restrict__ b1, const float* __restrict__ g1,
    const float* __restrict__ be1, const float* __restrict__ rm1, const float* __restrict__ rv1,
    const float* __restrict__ W2, const float* __restrict__ b2, const float* __restrict__ g2,
    const float* __restrict__ be2, const float* __restrict__ rm2, const float* __restrict__ rv2,
    const float* __restrict__ W3, const float* __restrict__ b3, const float* __restrict__ g3,
    const float* __restrict__ be3, const float* __restrict__ rm3, const float* __restrict__ rv3,
    const float* __restrict__ fW1, const float* __restrict__ fb1,
    const float* __restrict__ fW2, const float* __restrict__ fb2,
    const float* __restrict__ fW3, const float* __restrict__ fb3,
    const float* __restrict__ fW4, const float* __restrict__ fb4,
    float* __restrict__ out)
{
    __shared__ float Wm[18][18];
    __shared__ float A[18][18];          // A[c][r] = dinv[r]*w(r->c)*dinv[c]
    __shared__ float dinv[18];
    __shared__ float bns1[32], bnb1[32];
    __shared__ float bns2[64], bnb2[64];
    __shared__ float bns3[128], bnb3[128];
    __shared__ float buf1[18 * 128];
    __shared__ float buf2[18 * 128];
    __shared__ float pvec[128];
    __shared__ float m1[64], m2[32], m3[16];

    const int g = blockIdx.x;
    const int tid = threadIdx.x;

    // --- fold BN: s = gamma*rsqrt(var+eps), b = beta - mean*s ---
    if (tid < 32) {
        float s = g1[tid] * rsqrtf(rv1[tid] + BN_EPS);
        bns1[tid] = s; bnb1[tid] = be1[tid] - rm1[tid] * s;
    } else if (tid < 96) {
        int f = tid - 32;
        float s = g2[f] * rsqrtf(rv2[f] + BN_EPS);
        bns2[f] = s; bnb2[f] = be2[f] - rm2[f] * s;
    } else if (tid < 224) {
        int f = tid - 96;
        float s = g3[f] * rsqrtf(rv3[f] + BN_EPS);
        bns3[f] = s; bnb3[f] = be3[f] - rm3[f] * s;
    }

    // --- dense weighted adjacency (self-loop weight 1 on diagonal) ---
    // edge order from meshgrid('ij') with diag removed: e = s*17 + (d - (d>s))
    const float* ewg = ew + (size_t)g * EPERG;
    for (int t = tid; t < 324; t += 256) {
        int s = t / 18, d = t - s * 18;
        Wm[s][d] = (s == d) ? 1.0f : ewg[s * 17 + d - (d > s ? 1 : 0)];
    }
    __syncthreads();
    if (tid < 18) {
        float sum = 0.f;
#pragma unroll
        for (int s = 0; s < 18; s++) sum += Wm[s][tid];   // deg[col]
        dinv[tid] = rsqrtf(sum);                           // deg >= 1 always
    }
    __syncthreads();
    for (int t = tid; t < 324; t += 256) {
        int c = t / 18, r = t - c * 18;
        A[c][r] = dinv[r] * dinv[c] * Wm[r][c];
    }
    // load P1 rows for this graph into buf1[18][32] (stride 128)
    for (int t = tid; t < 18 * 32; t += 256) {
        int r = t >> 5, f = t & 31;
        buf1[r * 128 + f] = g_P1[((size_t)g * 18 + r) * 32 + f];
    }
    __syncthreads();

    // --- agg1 + bias + BN + lrelu -> buf2[18][32] ---
    for (int t = tid; t < 18 * 32; t += 256) {
        int c = t >> 5, f = t & 31;
        float acc = 0.f;
#pragma unroll
        for (int r = 0; r < 18; r++) acc += A[c][r] * buf1[r * 128 + f];
        float v = (acc + b1[f]) * bns1[f] + bnb1[f];
        buf2[c * 128 + f] = lrelu(v);
    }
    __syncthreads();

    // --- GEMM2: buf1[18][64] = buf2[18][32] @ W2[32][64] ---
    for (int t = tid; t < 18 * 64; t += 256) {
        int c = t >> 6, f = t & 63;
        float acc = 0.f;
#pragma unroll
        for (int k = 0; k < 32; k++) acc += buf2[c * 128 + k] * W2[k * 64 + f];
        buf1[c * 128 + f] = acc;
    }
    __syncthreads();

    // --- agg2 + bias + BN + lrelu -> buf2[18][64] ---
    for (int t = tid; t < 18 * 64; t += 256) {
        int c = t >> 6, f = t & 63;
        float acc = 0.f;
#pragma unroll
        for (int r = 0; r < 18; r++) acc += A[c][r] * buf1[r * 128 + f];
        float v = (acc + b2[f]) * bns2[f] + bnb2[f];
        buf2[c * 128 + f] = lrelu(v);
    }
    __syncthreads();

    // --- GEMM3: buf1[18][128] = buf2[18][64] @ W3[64][128] ---
    // column-parallel, all 18 rows register-blocked, K split across 2 groups
    {
        int grp = tid >> 7;           // 0 or 1
        int f = tid & 127;
        int kbase = grp * 32;
        float acc[18];
#pragma unroll
        for (int r = 0; r < 18; r++) acc[r] = 0.f;
        for (int k = 0; k < 32; k++) {
            float w = W3[(size_t)(kbase + k) * 128 + f];    // L1-resident
#pragma unroll
            for (int r = 0; r < 18; r++) acc[r] += buf2[r * 128 + kbase + k] * w;
        }
        if (grp == 0) {
#pragma unroll
            for (int r = 0; r < 18; r++) buf1[r * 128 + f] = acc[r];
        }
        __syncthreads();
        if (grp == 1) {
#pragma unroll
            for (int r = 0; r < 18; r++) buf1[r * 128 + f] += acc[r];
        }
    }
    __syncthreads();

    // --- agg3 + bias + BN + lrelu -> buf2[18][128], rows split across groups ---
    {
        int grp = tid >> 7;
        int f = tid & 127;
#pragma unroll
        for (int ci = 0; ci < 9; ci++) {
            int c = grp * 9 + ci;
            float acc = 0.f;
#pragma unroll
            for (int r = 0; r < 18; r++) acc += A[c][r] * buf1[r * 128 + f];
            float v = (acc + b3[f]) * bns3[f] + bnb3[f];
            buf2[c * 128 + f] = lrelu(v);
        }
    }
    __syncthreads();

    // --- global mean pool over 18 nodes ---
    if (tid < 128) {
        float s = 0.f;
#pragma unroll
        for (int r = 0; r < 18; r++) s += buf2[r * 128 + tid];
        pvec[tid] = s * (1.0f / 18.0f);
    }
    __syncthreads();

    // --- MLP head ---
    if (tid < 64) {
        float acc = fb1[tid];
#pragma unroll
        for (int k = 0; k < 128; k++) acc += pvec[k] * fW1[k * 64 + tid];
        m1[tid] = lrelu(acc);
    }
    __syncthreads();
    if (tid < 32) {
        float acc = fb2[tid];
#pragma unroll
        for (int k = 0; k < 64; k++) acc += m1[k] * fW2[k * 32 + tid];
        m2[tid] = lrelu(acc);
    }
    __syncthreads();
    if (tid < 16) {
        float acc = fb3[tid];
#pragma unroll
        for (int k = 0; k < 32; k++) acc += m2[k] * fW3[k * 16 + tid];
        m3[tid] = lrelu(acc);
    }
    __syncthreads();
    if (tid == 0) {
        float acc = fb4[0];
#pragma unroll
        for (int k = 0; k < 16; k++) acc += m3[k] * fW4[k];
        out[g] = acc;
    }
}

// ---------------------------------------------------------------------------
// Launch. Input order per metadata:
// 0 x, 1 edge_index, 2 edge_weight, 3 batch,
// 4 W1, 5 b1, 6 g1, 7 be1, 8 rm1, 9 rv1,
// 10 W2, 11 b2, 12 g2, 13 be2, 14 rm2, 15 rv2,
// 16 W3, 17 b3, 18 g3, 19 be3, 20 rm3, 21 rv3,
// 22 fW1, 23 fb1, 24 fW2, 25 fb2, 26 fW3, 27 fb3, 28 fW4, 29 fb4
// edge_index/batch are the fixed clique structure -> computed arithmetically.
// ---------------------------------------------------------------------------
extern "C" void kernel_launch(void* const* d_in, const int* in_sizes, int n_in,
                              void* d_out, int out_size)
{
    (void)in_sizes; (void)n_in; (void)out_size;
    const float* x   = (const float*)d_in[0];
    const float* ew  = (const float*)d_in[2];
    const float* W1  = (const float*)d_in[4];
    const float* b1  = (const float*)d_in[5];
    const float* g1  = (const float*)d_in[6];
    const float* be1 = (const float*)d_in[7];
    const float* rm1 = (const float*)d_in[8];
    const float* rv1 = (const float*)d_in[9];
    const float* W2  = (const float*)d_in[10];
    const float* b2  = (const float*)d_in[11];
    const float* g2  = (const float*)d_in[12];
    const float* be2 = (const float*)d_in[13];
    const float* rm2 = (const float*)d_in[14];
    const float* rv2 = (const float*)d_in[15];
    const float* W3  = (const float*)d_in[16];
    const float* b3  = (const float*)d_in[17];
    const float* g3  = (const float*)d_in[18];
    const float* be3 = (const float*)d_in[19];
    const float* rm3 = (const float*)d_in[20];
    const float* rv3 = (const float*)d_in[21];
    const float* fW1 = (const float*)d_in[22];
    const float* fb1 = (const float*)d_in[23];
    const float* fW2 = (const float*)d_in[24];
    const float* fb2 = (const float*)d_in[25];
    const float* fW3 = (const float*)d_in[26];
    const float* fb3 = (const float*)d_in[27];
    const float* fW4 = (const float*)d_in[28];
    const float* fb4 = (const float*)d_in[29];

    gemm1_kernel<<<NNODES / 128, 256>>>(x, W1);
    graph_kernel<<<GRAPHS, 256>>>(ew,
        b1, g1, be1, rm1, rv1,
        W2, b2, g2, be2, rm2, rv2,
        W3, b3, g3, be3, rm3, rv3,
        fW1, fb1, fW2, fb2, fW3, fb3, fW4, fb4,
        (float*)d_out);
}

// round 3
// speedup vs baseline: 1.7605x; 1.7605x over previous
#include <cuda_runtime.h>
#include <cuda_bf16.h>
#include <cstdint>

#define GRAPHS 4096
#define NPG 18
#define NNODES (GRAPHS * NPG)
#define FIN 1536
#define EPERG 306
#define SLOPE 0.01f
#define BN_EPS 1e-5f

#define CHUNK_K 64
#define NCHUNK (FIN / CHUNK_K)       // 24
#define APITCH 72                    // bf16 elems per smem row (64 + 8 pad) = 144B

// Scratch
__device__ float g_P1[(size_t)NNODES * 32];
__device__ __nv_bfloat16 g_WhiT[32 * FIN];   // W1 transposed [n][k], hi part
__device__ __nv_bfloat16 g_WloT[32 * FIN];   // lo part

// ---------------------------------------------------------------------------
// helpers (base sm_103 PTX only: ldmatrix + mma.sync)
// ---------------------------------------------------------------------------
__device__ __forceinline__ uint32_t smem_u32(const void* p) {
    uint32_t a;
    asm("{ .reg .u64 t; cvta.to.shared.u64 t, %1; cvt.u32.u64 %0, t; }" : "=r"(a) : "l"(p));
    return a;
}
__device__ __forceinline__ void ldm_x4(uint32_t* r, uint32_t addr) {
    asm volatile("ldmatrix.sync.aligned.m8n8.x4.shared.b16 {%0,%1,%2,%3}, [%4];"
        : "=r"(r[0]), "=r"(r[1]), "=r"(r[2]), "=r"(r[3]) : "r"(addr));
}
__device__ __forceinline__ void mma16816(float* c, const uint32_t* a, const uint32_t* b) {
    asm volatile("mma.sync.aligned.m16n8k16.row.col.f32.bf16.bf16.f32 "
        "{%0,%1,%2,%3}, {%4,%5,%6,%7}, {%8,%9}, {%0,%1,%2,%3};"
        : "+f"(c[0]), "+f"(c[1]), "+f"(c[2]), "+f"(c[3])
        : "r"(a[0]), "r"(a[1]), "r"(a[2]), "r"(a[3]), "r"(b[0]), "r"(b[1]));
}
// pack two f32 -> bf16x2 (lo arg -> low half, hi arg -> high half)
__device__ __forceinline__ uint32_t pack_bf16x2(float lo, float hi) {
    uint32_t r;
    asm("cvt.rn.bf16x2.f32 %0, %1, %2;" : "=r"(r) : "f"(hi), "f"(lo));
    return r;
}

// ---------------------------------------------------------------------------
// Kernel 0: split + transpose W1 -> bf16 hi/lo planes  [32][1536]
// ---------------------------------------------------------------------------
__global__ void wconv_kernel(const float* __restrict__ W1) {
    int idx = blockIdx.x * 256 + threadIdx.x;
    if (idx < FIN * 32) {
        int k = idx >> 5, n = idx & 31;
        float x = W1[idx];
        __nv_bfloat16 h = __float2bfloat16(x);
        float lo = x - __bfloat162float(h);
        g_WhiT[n * FIN + k] = h;
        g_WloT[n * FIN + k] = __float2bfloat16(lo);
    }
}

// ---------------------------------------------------------------------------
// Kernel 1: P1 = X @ W1 via mma.sync bf16 split (3 products, fp32 reg accum).
// CTA: 256 thr (8 warps), tile M=128 N=32, K-chunks of 64, warp = 16 rows.
// ---------------------------------------------------------------------------
__global__ __launch_bounds__(256, 2) void gemm1_mma_kernel(const float* __restrict__ X)
{
    __shared__ __align__(16) __nv_bfloat16 sAhi[128 * APITCH];  // 18 KB
    __shared__ __align__(16) __nv_bfloat16 sAlo[128 * APITCH];  // 18 KB
    __shared__ __align__(16) __nv_bfloat16 sBhi[32 * APITCH];   // 4.5 KB
    __shared__ __align__(16) __nv_bfloat16 sBlo[32 * APITCH];   // 4.5 KB

    const int tid = threadIdx.x;
    const int wid = tid >> 5;
    const int lane = tid & 31;
    const int row0 = blockIdx.x * 128;
    const int m0 = wid * 16;

    const uint32_t a_ahi = smem_u32(sAhi), a_alo = smem_u32(sAlo);
    const uint32_t a_bhi = smem_u32(sBhi), a_blo = smem_u32(sBlo);

    // B gmem-load geometry: n = tid>>3 (0..31), kc = tid&7 (16B chunk)
    const int bn = tid >> 3, bc = tid & 7;

    float acc[4][4];
#pragma unroll
    for (int nt = 0; nt < 4; nt++)
#pragma unroll
        for (int q = 0; q < 4; q++) acc[nt][q] = 0.f;

    // ldmatrix A address offset (bytes), fixed per thread up to k0 shift:
    //   row = m0 + (lane & 15), col(k) = (lane>>4)*8
    const uint32_t a_off_base = (uint32_t)(m0 + (lane & 15)) * (APITCH * 2)
                              + (uint32_t)((lane >> 4) * 8) * 2;

#pragma unroll 1
    for (int i = 0; i < NCHUNK; i++) {
        // ---- prefetch gmem into regs (overlaps previous chunk's mma) ----
        float4 va[8];
#pragma unroll
        for (int j = 0; j < 8; j++) {
            int idx = tid + j * 256;
            int r = idx >> 4, c = idx & 15;
            va[j] = *(const float4*)(X + (size_t)(row0 + r) * FIN + i * CHUNK_K + c * 4);
        }
        uint4 vbh = *(const uint4*)(g_WhiT + bn * FIN + i * CHUNK_K + bc * 8);
        uint4 vbl = *(const uint4*)(g_WloT + bn * FIN + i * CHUNK_K + bc * 8);

        __syncthreads();   // previous chunk's ldmatrix reads complete

        // ---- split-convert + store A ----
#pragma unroll
        for (int j = 0; j < 8; j++) {
            int idx = tid + j * 256;
            int r = idx >> 4, c = idx & 15;
            float4 v = va[j];
            uint32_t h01 = pack_bf16x2(v.x, v.y);
            uint32_t h23 = pack_bf16x2(v.z, v.w);
            float f0 = __uint_as_float(h01 << 16);
            float f1 = __uint_as_float(h01 & 0xFFFF0000u);
            float f2 = __uint_as_float(h23 << 16);
            float f3 = __uint_as_float(h23 & 0xFFFF0000u);
            uint32_t l01 = pack_bf16x2(v.x - f0, v.y - f1);
            uint32_t l23 = pack_bf16x2(v.z - f2, v.w - f3);
            uint32_t bo = (uint32_t)r * (APITCH * 2) + (uint32_t)c * 8;
            *(uint2*)((char*)sAhi + bo) = make_uint2(h01, h23);
            *(uint2*)((char*)sAlo + bo) = make_uint2(l01, l23);
        }
        // ---- store B planes ----
        {
            uint32_t bo = (uint32_t)bn * (APITCH * 2) + (uint32_t)bc * 16;
            *(uint4*)((char*)sBhi + bo) = vbh;
            *(uint4*)((char*)sBlo + bo) = vbl;
        }
        __syncthreads();

        // ---- compute: 4 k-steps of 16 ----
#pragma unroll
        for (int ks = 0; ks < 4; ks++) {
            uint32_t aoff = a_off_base + (uint32_t)(ks * 16) * 2;
            uint32_t ahi[4], alo[4];
            ldm_x4(ahi, a_ahi + aoff);
            ldm_x4(alo, a_alo + aoff);

            // B: two x4 loads per plane cover 4 n-tiles
            uint32_t bhi[8], blo[8];
#pragma unroll
            for (int p = 0; p < 2; p++) {
                int grp = lane >> 3;
                int n = p * 16 + (grp >> 1) * 8 + (lane & 7);
                int kk = ks * 16 + (grp & 1) * 8;
                uint32_t boff = (uint32_t)n * (APITCH * 2) + (uint32_t)kk * 2;
                ldm_x4(bhi + p * 4, a_bhi + boff);
                ldm_x4(blo + p * 4, a_blo + boff);
            }
#pragma unroll
            for (int nt = 0; nt < 4; nt++) {
                mma16816(acc[nt], ahi, bhi + nt * 2);
                mma16816(acc[nt], ahi, blo + nt * 2);
                mma16816(acc[nt], alo, bhi + nt * 2);
            }
        }
    }

    // ---- epilogue: C fragment -> g_P1 ----
    {
        int r = row0 + m0 + (lane >> 2);
        int cb = (lane & 3) * 2;
#pragma unroll
        for (int nt = 0; nt < 4; nt++) {
            *(float2*)(g_P1 + (size_t)r * 32 + nt * 8 + cb) =
                make_float2(acc[nt][0], acc[nt][1]);
            *(float2*)(g_P1 + (size_t)(r + 8) * 32 + nt * 8 + cb) =
                make_float2(acc[nt][2], acc[nt][3]);
        }
    }
}

// ---------------------------------------------------------------------------
// Kernel 2: per-graph fused GCN layers + pooling + MLP head (unchanged)
// ---------------------------------------------------------------------------
__device__ __forceinline__ float lrelu(float v) { return v >= 0.f ? v : SLOPE * v; }

__global__ __launch_bounds__(256) void graph_kernel(
    const float* __restrict__ ew,
    const float* __restrict__ b1, const float* __restrict__ g1,
    const float* __restrict__ be1, const float* __restrict__ rm1, const float* __restrict__ rv1,
    const float* __restrict__ W2, const float* __restrict__ b2, const float* __restrict__ g2,
    const float* __restrict__ be2, const float* __restrict__ rm2, const float* __restrict__ rv2,
    const float* __restrict__ W3, const float* __restrict__ b3, const float* __restrict__ g3,
    const float* __restrict__ be3, const float* __restrict__ rm3, const float* __restrict__ rv3,
    const float* __restrict__ fW1, const float* __restrict__ fb1,
    const float* __restrict__ fW2, const float* __restrict__ fb2,
    const float* __restrict__ fW3, const float* __restrict__ fb3,
    const float* __restrict__ fW4, const float* __restrict__ fb4,
    float* __restrict__ out)
{
    __shared__ float Wm[18][18];
    __shared__ float A[18][18];
    __shared__ float dinv[18];
    __shared__ float bns1[32], bnb1[32];
    __shared__ float bns2[64], bnb2[64];
    __shared__ float bns3[128], bnb3[128];
    __shared__ float buf1[18 * 128];
    __shared__ float buf2[18 * 128];
    __shared__ float pvec[128];
    __shared__ float m1[64], m2[32], m3[16];

    const int g = blockIdx.x;
    const int tid = threadIdx.x;

    if (tid < 32) {
        float s = g1[tid] * rsqrtf(rv1[tid] + BN_EPS);
        bns1[tid] = s; bnb1[tid] = be1[tid] - rm1[tid] * s;
    } else if (tid < 96) {
        int f = tid - 32;
        float s = g2[f] * rsqrtf(rv2[f] + BN_EPS);
        bns2[f] = s; bnb2[f] = be2[f] - rm2[f] * s;
    } else if (tid < 224) {
        int f = tid - 96;
        float s = g3[f] * rsqrtf(rv3[f] + BN_EPS);
        bns3[f] = s; bnb3[f] = be3[f] - rm3[f] * s;
    }

    const float* ewg = ew + (size_t)g * EPERG;
    for (int t = tid; t < 324; t += 256) {
        int s = t / 18, d = t - s * 18;
        Wm[s][d] = (s == d) ? 1.0f : ewg[s * 17 + d - (d > s ? 1 : 0)];
    }
    __syncthreads();
    if (tid < 18) {
        float sum = 0.f;
#pragma unroll
        for (int s = 0; s < 18; s++) sum += Wm[s][tid];
        dinv[tid] = rsqrtf(sum);
    }
    __syncthreads();
    for (int t = tid; t < 324; t += 256) {
        int c = t / 18, r = t - c * 18;
        A[c][r] = dinv[r] * dinv[c] * Wm[r][c];
    }
    for (int t = tid; t < 18 * 32; t += 256) {
        int r = t >> 5, f = t & 31;
        buf1[r * 128 + f] = g_P1[((size_t)g * 18 + r) * 32 + f];
    }
    __syncthreads();

    for (int t = tid; t < 18 * 32; t += 256) {
        int c = t >> 5, f = t & 31;
        float acc = 0.f;
#pragma unroll
        for (int r = 0; r < 18; r++) acc += A[c][r] * buf1[r * 128 + f];
        float v = (acc + b1[f]) * bns1[f] + bnb1[f];
        buf2[c * 128 + f] = lrelu(v);
    }
    __syncthreads();

    for (int t = tid; t < 18 * 64; t += 256) {
        int c = t >> 6, f = t & 63;
        float acc = 0.f;
#pragma unroll
        for (int k = 0; k < 32; k++) acc += buf2[c * 128 + k] * W2[k * 64 + f];
        buf1[c * 128 + f] = acc;
    }
    __syncthreads();

    for (int t = tid; t < 18 * 64; t += 256) {
        int c = t >> 6, f = t & 63;
        float acc = 0.f;
#pragma unroll
        for (int r = 0; r < 18; r++) acc += A[c][r] * buf1[r * 128 + f];
        float v = (acc + b2[f]) * bns2[f] + bnb2[f];
        buf2[c * 128 + f] = lrelu(v);
    }
    __syncthreads();

    {
        int grp = tid >> 7;
        int f = tid & 127;
        int kbase = grp * 32;
        float acc[18];
#pragma unroll
        for (int r = 0; r < 18; r++) acc[r] = 0.f;
        for (int k = 0; k < 32; k++) {
            float w = W3[(size_t)(kbase + k) * 128 + f];
#pragma unroll
            for (int r = 0; r < 18; r++) acc[r] += buf2[r * 128 + kbase + k] * w;
        }
        if (grp == 0) {
#pragma unroll
            for (int r = 0; r < 18; r++) buf1[r * 128 + f] = acc[r];
        }
        __syncthreads();
        if (grp == 1) {
#pragma unroll
            for (int r = 0; r < 18; r++) buf1[r * 128 + f] += acc[r];
        }
    }
    __syncthreads();

    {
        int grp = tid >> 7;
        int f = tid & 127;
#pragma unroll
        for (int ci = 0; ci < 9; ci++) {
            int c = grp * 9 + ci;
            float acc = 0.f;
#pragma unroll
            for (int r = 0; r < 18; r++) acc += A[c][r] * buf1[r * 128 + f];
            float v = (acc + b3[f]) * bns3[f] + bnb3[f];
            buf2[c * 128 + f] = lrelu(v);
        }
    }
    __syncthreads();

    if (tid < 128) {
        float s = 0.f;
#pragma unroll
        for (int r = 0; r < 18; r++) s += buf2[r * 128 + tid];
        pvec[tid] = s * (1.0f / 18.0f);
    }
    __syncthreads();

    if (tid < 64) {
        float acc = fb1[tid];
#pragma unroll
        for (int k = 0; k < 128; k++) acc += pvec[k] * fW1[k * 64 + tid];
        m1[tid] = lrelu(acc);
    }
    __syncthreads();
    if (tid < 32) {
        float acc = fb2[tid];
#pragma unroll
        for (int k = 0; k < 64; k++) acc += m1[k] * fW2[k * 32 + tid];
        m2[tid] = lrelu(acc);
    }
    __syncthreads();
    if (tid < 16) {
        float acc = fb3[tid];
#pragma unroll
        for (int k = 0; k < 32; k++) acc += m2[k] * fW3[k * 16 + tid];
        m3[tid] = lrelu(acc);
    }
    __syncthreads();
    if (tid == 0) {
        float acc = fb4[0];
#pragma unroll
        for (int k = 0; k < 16; k++) acc += m3[k] * fW4[k];
        out[g] = acc;
    }
}

// ---------------------------------------------------------------------------
extern "C" void kernel_launch(void* const* d_in, const int* in_sizes, int n_in,
                              void* d_out, int out_size)
{
    (void)in_sizes; (void)n_in; (void)out_size;
    const float* x   = (const float*)d_in[0];
    const float* ew  = (const float*)d_in[2];
    const float* W1  = (const float*)d_in[4];
    const float* b1  = (const float*)d_in[5];
    const float* g1  = (const float*)d_in[6];
    const float* be1 = (const float*)d_in[7];
    const float* rm1 = (const float*)d_in[8];
    const float* rv1 = (const float*)d_in[9];
    const float* W2  = (const float*)d_in[10];
    const float* b2  = (const float*)d_in[11];
    const float* g2  = (const float*)d_in[12];
    const float* be2 = (const float*)d_in[13];
    const float* rm2 = (const float*)d_in[14];
    const float* rv2 = (const float*)d_in[15];
    const float* W3  = (const float*)d_in[16];
    const float* b3  = (const float*)d_in[17];
    const float* g3  = (const float*)d_in[18];
    const float* be3 = (const float*)d_in[19];
    const float* rm3 = (const float*)d_in[20];
    const float* rv3 = (const float*)d_in[21];
    const float* fW1 = (const float*)d_in[22];
    const float* fb1 = (const float*)d_in[23];
    const float* fW2 = (const float*)d_in[24];
    const float* fb2 = (const float*)d_in[25];
    const float* fW3 = (const float*)d_in[26];
    const float* fb3 = (const float*)d_in[27];
    const float* fW4 = (const float*)d_in[28];
    const float* fb4 = (const float*)d_in[29];

    wconv_kernel<<<192, 256>>>(W1);
    gemm1_mma_kernel<<<NNODES / 128, 256>>>(x);
    graph_kernel<<<GRAPHS, 256>>>(ew,
        b1, g1, be1, rm1, rv1,
        W2, b2, g2, be2, rm2, rv2,
        W3, b3, g3, be3, rm3, rv3,
        fW1, fb1, fW2, fb2, fW3, fb3, fW4, fb4,
        (float*)d_out);
}

// round 4
// speedup vs baseline: 1.8340x; 1.0417x over previous
#include <cuda_runtime.h>
#include <cuda_bf16.h>
#include <cstdint>

#define GRAPHS 4096
#define NPG 18
#define NNODES (GRAPHS * NPG)
#define FIN 1536
#define EPERG 306
#define SLOPE 0.01f
#define BN_EPS 1e-5f

#define CHUNK_K 64
#define NCHUNK (FIN / CHUNK_K)       // 24
#define APITCH 72                    // bf16 elems per smem row (64 + 8 pad) = 144B

// Scratch
__device__ float g_P1[(size_t)NNODES * 32];
__device__ __nv_bfloat16 g_WhiT[32 * FIN];   // W1 transposed [n][k], hi part
__device__ __nv_bfloat16 g_WloT[32 * FIN];   // lo part

// ---------------------------------------------------------------------------
// helpers (base sm_103 PTX only: ldmatrix + mma.sync)
// ---------------------------------------------------------------------------
__device__ __forceinline__ uint32_t smem_u32(const void* p) {
    uint32_t a;
    asm("{ .reg .u64 t; cvta.to.shared.u64 t, %1; cvt.u32.u64 %0, t; }" : "=r"(a) : "l"(p));
    return a;
}
__device__ __forceinline__ void ldm_x4(uint32_t* r, uint32_t addr) {
    asm volatile("ldmatrix.sync.aligned.m8n8.x4.shared.b16 {%0,%1,%2,%3}, [%4];"
        : "=r"(r[0]), "=r"(r[1]), "=r"(r[2]), "=r"(r[3]) : "r"(addr));
}
__device__ __forceinline__ void mma16816(float* c, const uint32_t* a, const uint32_t* b) {
    asm volatile("mma.sync.aligned.m16n8k16.row.col.f32.bf16.bf16.f32 "
        "{%0,%1,%2,%3}, {%4,%5,%6,%7}, {%8,%9}, {%0,%1,%2,%3};"
        : "+f"(c[0]), "+f"(c[1]), "+f"(c[2]), "+f"(c[3])
        : "r"(a[0]), "r"(a[1]), "r"(a[2]), "r"(a[3]), "r"(b[0]), "r"(b[1]));
}
__device__ __forceinline__ uint32_t pack_bf16x2(float lo, float hi) {
    uint32_t r;
    asm("cvt.rn.bf16x2.f32 %0, %1, %2;" : "=r"(r) : "f"(hi), "f"(lo));
    return r;
}

// ---------------------------------------------------------------------------
// Kernel 0: split + transpose W1 -> bf16 hi/lo planes  [32][1536]
// CTA handles 64 k-rows; smem tile transpose; coalesced uint4 stores.
// ---------------------------------------------------------------------------
__global__ __launch_bounds__(256) void wconv_kernel(const float* __restrict__ W1) {
    __shared__ float t[64][33];
    const int tid = threadIdx.x;
    const int k0 = blockIdx.x * 64;
#pragma unroll
    for (int j = 0; j < 2; j++) {
        int idx = tid + j * 256;            // 0..511
        int kr = idx >> 3, nf4 = idx & 7;
        float4 v = *(const float4*)(W1 + (size_t)(k0 + kr) * 32 + nf4 * 4);
        t[kr][nf4 * 4 + 0] = v.x; t[kr][nf4 * 4 + 1] = v.y;
        t[kr][nf4 * 4 + 2] = v.z; t[kr][nf4 * 4 + 3] = v.w;
    }
    __syncthreads();
    const int n = tid >> 3, kg = tid & 7;
    unsigned short hs[8], ls[8];
#pragma unroll
    for (int kk = 0; kk < 8; kk++) {
        float x = t[kg * 8 + kk][n];
        __nv_bfloat16 h = __float2bfloat16(x);
        __nv_bfloat16 l = __float2bfloat16(x - __bfloat162float(h));
        hs[kk] = *(unsigned short*)&h;
        ls[kk] = *(unsigned short*)&l;
    }
    size_t o = (size_t)n * FIN + k0 + kg * 8;
    *(uint4*)(g_WhiT + o) = *(uint4*)hs;
    *(uint4*)(g_WloT + o) = *(uint4*)ls;
}

// ---------------------------------------------------------------------------
// Kernel 1: P1 = X @ W1 via mma.sync bf16 split (unchanged from round 3)
// ---------------------------------------------------------------------------
__global__ __launch_bounds__(256, 2) void gemm1_mma_kernel(const float* __restrict__ X)
{
    __shared__ __align__(16) __nv_bfloat16 sAhi[128 * APITCH];
    __shared__ __align__(16) __nv_bfloat16 sAlo[128 * APITCH];
    __shared__ __align__(16) __nv_bfloat16 sBhi[32 * APITCH];
    __shared__ __align__(16) __nv_bfloat16 sBlo[32 * APITCH];

    const int tid = threadIdx.x;
    const int wid = tid >> 5;
    const int lane = tid & 31;
    const int row0 = blockIdx.x * 128;
    const int m0 = wid * 16;

    const uint32_t a_ahi = smem_u32(sAhi), a_alo = smem_u32(sAlo);
    const uint32_t a_bhi = smem_u32(sBhi), a_blo = smem_u32(sBlo);

    const int bn = tid >> 3, bc = tid & 7;

    float acc[4][4];
#pragma unroll
    for (int nt = 0; nt < 4; nt++)
#pragma unroll
        for (int q = 0; q < 4; q++) acc[nt][q] = 0.f;

    const uint32_t a_off_base = (uint32_t)(m0 + (lane & 15)) * (APITCH * 2)
                              + (uint32_t)((lane >> 4) * 8) * 2;

#pragma unroll 1
    for (int i = 0; i < NCHUNK; i++) {
        float4 va[8];
#pragma unroll
        for (int j = 0; j < 8; j++) {
            int idx = tid + j * 256;
            int r = idx >> 4, c = idx & 15;
            va[j] = *(const float4*)(X + (size_t)(row0 + r) * FIN + i * CHUNK_K + c * 4);
        }
        uint4 vbh = *(const uint4*)(g_WhiT + bn * FIN + i * CHUNK_K + bc * 8);
        uint4 vbl = *(const uint4*)(g_WloT + bn * FIN + i * CHUNK_K + bc * 8);

        __syncthreads();

#pragma unroll
        for (int j = 0; j < 8; j++) {
            int idx = tid + j * 256;
            int r = idx >> 4, c = idx & 15;
            float4 v = va[j];
            uint32_t h01 = pack_bf16x2(v.x, v.y);
            uint32_t h23 = pack_bf16x2(v.z, v.w);
            float f0 = __uint_as_float(h01 << 16);
            float f1 = __uint_as_float(h01 & 0xFFFF0000u);
            float f2 = __uint_as_float(h23 << 16);
            float f3 = __uint_as_float(h23 & 0xFFFF0000u);
            uint32_t l01 = pack_bf16x2(v.x - f0, v.y - f1);
            uint32_t l23 = pack_bf16x2(v.z - f2, v.w - f3);
            uint32_t bo = (uint32_t)r * (APITCH * 2) + (uint32_t)c * 8;
            *(uint2*)((char*)sAhi + bo) = make_uint2(h01, h23);
            *(uint2*)((char*)sAlo + bo) = make_uint2(l01, l23);
        }
        {
            uint32_t bo = (uint32_t)bn * (APITCH * 2) + (uint32_t)bc * 16;
            *(uint4*)((char*)sBhi + bo) = vbh;
            *(uint4*)((char*)sBlo + bo) = vbl;
        }
        __syncthreads();

#pragma unroll
        for (int ks = 0; ks < 4; ks++) {
            uint32_t aoff = a_off_base + (uint32_t)(ks * 16) * 2;
            uint32_t ahi[4], alo[4];
            ldm_x4(ahi, a_ahi + aoff);
            ldm_x4(alo, a_alo + aoff);

            uint32_t bhi[8], blo[8];
#pragma unroll
            for (int p = 0; p < 2; p++) {
                int grp = lane >> 3;
                int n = p * 16 + (grp >> 1) * 8 + (lane & 7);
                int kk = ks * 16 + (grp & 1) * 8;
                uint32_t boff = (uint32_t)n * (APITCH * 2) + (uint32_t)kk * 2;
                ldm_x4(bhi + p * 4, a_bhi + boff);
                ldm_x4(blo + p * 4, a_blo + boff);
            }
#pragma unroll
            for (int nt = 0; nt < 4; nt++) {
                mma16816(acc[nt], ahi, bhi + nt * 2);
                mma16816(acc[nt], ahi, blo + nt * 2);
                mma16816(acc[nt], alo, bhi + nt * 2);
            }
        }
    }

    {
        int r = row0 + m0 + (lane >> 2);
        int cb = (lane & 3) * 2;
#pragma unroll
        for (int nt = 0; nt < 4; nt++) {
            *(float2*)(g_P1 + (size_t)r * 32 + nt * 8 + cb) =
                make_float2(acc[nt][0], acc[nt][1]);
            *(float2*)(g_P1 + (size_t)(r + 8) * 32 + nt * 8 + cb) =
                make_float2(acc[nt][2], acc[nt][3]);
        }
    }
}

// ---------------------------------------------------------------------------
// Kernel 2: per-graph fused pipeline, 288 threads, float4-vectorized,
// aggregate-then-transform ordering for layers 2/3.
// ---------------------------------------------------------------------------
__device__ __forceinline__ float lrelu(float v) { return v >= 0.f ? v : SLOPE * v; }
__device__ __forceinline__ float4 f4fma(float a, float4 b, float4 c) {
    return make_float4(fmaf(a, b.x, c.x), fmaf(a, b.y, c.y),
                       fmaf(a, b.z, c.z), fmaf(a, b.w, c.w));
}

__global__ __launch_bounds__(288, 4) void graph_kernel(
    const float* __restrict__ ew,
    const float* __restrict__ b1, const float* __restrict__ g1,
    const float* __restrict__ be1, const float* __restrict__ rm1, const float* __restrict__ rv1,
    const float* __restrict__ W2, const float* __restrict__ b2, const float* __restrict__ g2,
    const float* __restrict__ be2, const float* __restrict__ rm2, const float* __restrict__ rv2,
    const float* __restrict__ W3, const float* __restrict__ b3, const float* __restrict__ g3,
    const float* __restrict__ be3, const float* __restrict__ rm3, const float* __restrict__ rv3,
    const float* __restrict__ fW1, const float* __restrict__ fb1,
    const float* __restrict__ fW2, const float* __restrict__ fb2,
    const float* __restrict__ fW3, const float* __restrict__ fb3,
    const float* __restrict__ fW4, const float* __restrict__ fb4,
    float* __restrict__ out)
{
    __shared__ __align__(16) float Wm[18][20];
    __shared__ __align__(16) float A[18][20];     // A[c][r]
    __shared__ float dinv[18];
    __shared__ __align__(16) float bns1[32], bnb1[32];
    __shared__ __align__(16) float bns2[64], bnb2[64];
    __shared__ __align__(16) float bns3[128], bnb3[128];
    __shared__ __align__(16) float bufA[18 * 128];
    __shared__ __align__(16) float bufB[18 * 128];
    __shared__ __align__(16) float pvec[128];
    __shared__ __align__(16) float part[4][64];
    __shared__ float m1[64], m2[32], m3[16];

    const int g = blockIdx.x;
    const int tid = threadIdx.x;

    // --- fold BN constants ---
    if (tid < 32) {
        float s = g1[tid] * rsqrtf(rv1[tid] + BN_EPS);
        bns1[tid] = s; bnb1[tid] = be1[tid] - rm1[tid] * s;
    } else if (tid < 96) {
        int f = tid - 32;
        float s = g2[f] * rsqrtf(rv2[f] + BN_EPS);
        bns2[f] = s; bnb2[f] = be2[f] - rm2[f] * s;
    } else if (tid < 224) {
        int f = tid - 96;
        float s = g3[f] * rsqrtf(rv3[f] + BN_EPS);
        bns3[f] = s; bnb3[f] = be3[f] - rm3[f] * s;
    }

    // --- adjacency ---
    const float* ewg = ew + (size_t)g * EPERG;
    for (int t = tid; t < 324; t += 288) {
        int s = t / 18, d = t - s * 18;
        Wm[s][d] = (s == d) ? 1.0f : ewg[s * 17 + d - (d > s ? 1 : 0)];
    }
    // load P1 rows -> bufA[18][32]
    if (tid < 144) {
        int r = tid >> 3, f4 = tid & 7;
        *(float4*)&bufA[r * 128 + f4 * 4] =
            *(const float4*)(g_P1 + ((size_t)g * 18 + r) * 32 + f4 * 4);
    }
    __syncthreads();
    if (tid < 18) {
        float sum = 0.f;
#pragma unroll
        for (int s = 0; s < 18; s++) sum += Wm[s][tid];
        dinv[tid] = rsqrtf(sum);
    }
    __syncthreads();
    for (int t = tid; t < 324; t += 288) {
        int c = t / 18, r = t - c * 18;
        A[c][r] = dinv[r] * dinv[c] * Wm[r][c];
    }
    __syncthreads();

    // --- layer1: h1 = lrelu(bn1(A @ P1 + b1)) -> bufB[18][32] ---
    if (tid < 144) {
        int c = tid >> 3, f4 = tid & 7;
        float4 acc = make_float4(0.f, 0.f, 0.f, 0.f);
#pragma unroll
        for (int r = 0; r < 18; r++)
            acc = f4fma(A[c][r], *(float4*)&bufA[r * 128 + f4 * 4], acc);
        float4 bb = __ldg((const float4*)(b1) + f4);
        float4 s = *(float4*)&bns1[f4 * 4];
        float4 t = *(float4*)&bnb1[f4 * 4];
        float4 o;
        o.x = lrelu(fmaf(acc.x + bb.x, s.x, t.x));
        o.y = lrelu(fmaf(acc.y + bb.y, s.y, t.y));
        o.z = lrelu(fmaf(acc.z + bb.z, s.z, t.z));
        o.w = lrelu(fmaf(acc.w + bb.w, s.w, t.w));
        *(float4*)&bufB[c * 128 + f4 * 4] = o;
    }
    __syncthreads();

    // --- layer2 agg-first: g2m = A @ h1 -> bufA[18][32] ---
    if (tid < 144) {
        int c = tid >> 3, f4 = tid & 7;
        float4 acc = make_float4(0.f, 0.f, 0.f, 0.f);
#pragma unroll
        for (int r = 0; r < 18; r++)
            acc = f4fma(A[c][r], *(float4*)&bufB[r * 128 + f4 * 4], acc);
        *(float4*)&bufA[c * 128 + f4 * 4] = acc;
    }
    __syncthreads();

    // --- layer2 GEMM: h2 = lrelu(bn2(g2m @ W2 + b2)) -> bufB[18][64] ---
    {
        int c = tid >> 4, f4 = tid & 15;     // 18 x 16 = 288 exact
        float4 acc = make_float4(0.f, 0.f, 0.f, 0.f);
#pragma unroll
        for (int k = 0; k < 32; k++)
            acc = f4fma(bufA[c * 128 + k], __ldg((const float4*)(W2 + k * 64) + f4), acc);
        float4 bb = __ldg((const float4*)(b2) + f4);
        float4 s = *(float4*)&bns2[f4 * 4];
        float4 t = *(float4*)&bnb2[f4 * 4];
        float4 o;
        o.x = lrelu(fmaf(acc.x + bb.x, s.x, t.x));
        o.y = lrelu(fmaf(acc.y + bb.y, s.y, t.y));
        o.z = lrelu(fmaf(acc.z + bb.z, s.z, t.z));
        o.w = lrelu(fmaf(acc.w + bb.w, s.w, t.w));
        *(float4*)&bufB[c * 128 + f4 * 4] = o;
    }
    __syncthreads();

    // --- layer3 agg-first: g3m = A @ h2 -> bufA[18][64] ---
    {
        int c = tid >> 4, f4 = tid & 15;
        float4 acc = make_float4(0.f, 0.f, 0.f, 0.f);
#pragma unroll
        for (int r = 0; r < 18; r++)
            acc = f4fma(A[c][r], *(float4*)&bufB[r * 128 + f4 * 4], acc);
        *(float4*)&bufA[c * 128 + f4 * 4] = acc;
    }
    __syncthreads();

    // --- layer3 GEMM: h3 = lrelu(bn3(g3m @ W3 + b3)) -> bufB[18][128] ---
    {
        int cg = tid >> 5, f4 = tid & 31;    // 9 x 32 = 288; warp == cg
        int c0 = cg * 2, c1 = c0 + 1;
        float4 acc0 = make_float4(0.f, 0.f, 0.f, 0.f);
        float4 acc1 = make_float4(0.f, 0.f, 0.f, 0.f);
#pragma unroll 8
        for (int k = 0; k < 64; k++) {
            float4 w = __ldg((const float4*)(W3 + (size_t)k * 128) + f4);
            acc0 = f4fma(bufA[c0 * 128 + k], w, acc0);
            acc1 = f4fma(bufA[c1 * 128 + k], w, acc1);
        }
        float4 bb = __ldg((const float4*)(b3) + f4);
        float4 s = *(float4*)&bns3[f4 * 4];
        float4 t = *(float4*)&bnb3[f4 * 4];
        float4 o0, o1;
        o0.x = lrelu(fmaf(acc0.x + bb.x, s.x, t.x));
        o0.y = lrelu(fmaf(acc0.y + bb.y, s.y, t.y));
        o0.z = lrelu(fmaf(acc0.z + bb.z, s.z, t.z));
        o0.w = lrelu(fmaf(acc0.w + bb.w, s.w, t.w));
        o1.x = lrelu(fmaf(acc1.x + bb.x, s.x, t.x));
        o1.y = lrelu(fmaf(acc1.y + bb.y, s.y, t.y));
        o1.z = lrelu(fmaf(acc1.z + bb.z, s.z, t.z));
        o1.w = lrelu(fmaf(acc1.w + bb.w, s.w, t.w));
        *(float4*)&bufB[c0 * 128 + f4 * 4] = o0;
        *(float4*)&bufB[c1 * 128 + f4 * 4] = o1;
    }
    __syncthreads();

    // --- mean pool over 18 nodes ---
    if (tid < 128) {
        float s = 0.f;
#pragma unroll
        for (int r = 0; r < 18; r++) s += bufB[r * 128 + tid];
        pvec[tid] = s * (1.0f / 18.0f);
    }
    __syncthreads();

    // --- MLP head: fW1 (128->64), 4-way k-split ---
    if (tid < 256) {
        int f = tid & 63, kc = tid >> 6;
        float acc = 0.f;
#pragma unroll
        for (int k = kc * 32; k < kc * 32 + 32; k++)
            acc = fmaf(pvec[k], __ldg(fW1 + (size_t)k * 64 + f), acc);
        part[kc][f] = acc;
    }
    __syncthreads();
    if (tid < 64) {
        float v = part[0][tid] + part[1][tid] + part[2][tid] + part[3][tid] + __ldg(fb1 + tid);
        m1[tid] = lrelu(v);
    }
    __syncthreads();
    if (tid < 32) {
        float acc = __ldg(fb2 + tid);
#pragma unroll
        for (int k = 0; k < 64; k++) acc = fmaf(m1[k], __ldg(fW2 + (size_t)k * 32 + tid), acc);
        m2[tid] = lrelu(acc);
    }
    __syncthreads();
    if (tid < 16) {
        float acc = __ldg(fb3 + tid);
#pragma unroll
        for (int k = 0; k < 32; k++) acc = fmaf(m2[k], __ldg(fW3 + (size_t)k * 16 + tid), acc);
        m3[tid] = lrelu(acc);
    }
    __syncthreads();
    if (tid < 32) {
        float p = (tid < 16) ? m3[tid] * __ldg(fW4 + tid) : 0.f;
#pragma unroll
        for (int off = 8; off > 0; off >>= 1)
            p += __shfl_down_sync(0xFFFFFFFFu, p, off);
        if (tid == 0) out[g] = p + __ldg(fb4);
    }
}

// ---------------------------------------------------------------------------
extern "C" void kernel_launch(void* const* d_in, const int* in_sizes, int n_in,
                              void* d_out, int out_size)
{
    (void)in_sizes; (void)n_in; (void)out_size;
    const float* x   = (const float*)d_in[0];
    const float* ew  = (const float*)d_in[2];
    const float* W1  = (const float*)d_in[4];
    const float* b1  = (const float*)d_in[5];
    const float* g1  = (const float*)d_in[6];
    const float* be1 = (const float*)d_in[7];
    const float* rm1 = (const float*)d_in[8];
    const float* rv1 = (const float*)d_in[9];
    const float* W2  = (const float*)d_in[10];
    const float* b2  = (const float*)d_in[11];
    const float* g2  = (const float*)d_in[12];
    const float* be2 = (const float*)d_in[13];
    const float* rm2 = (const float*)d_in[14];
    const float* rv2 = (const float*)d_in[15];
    const float* W3  = (const float*)d_in[16];
    const float* b3  = (const float*)d_in[17];
    const float* g3  = (const float*)d_in[18];
    const float* be3 = (const float*)d_in[19];
    const float* rm3 = (const float*)d_in[20];
    const float* rv3 = (const float*)d_in[21];
    const float* fW1 = (const float*)d_in[22];
    const float* fb1 = (const float*)d_in[23];
    const float* fW2 = (const float*)d_in[24];
    const float* fb2 = (const float*)d_in[25];
    const float* fW3 = (const float*)d_in[26];
    const float* fb3 = (const float*)d_in[27];
    const float* fW4 = (const float*)d_in[28];
    const float* fb4 = (const float*)d_in[29];

    wconv_kernel<<<FIN / 64, 256>>>(W1);
    gemm1_mma_kernel<<<NNODES / 128, 256>>>(x);
    graph_kernel<<<GRAPHS, 288>>>(ew,
        b1, g1, be1, rm1, rv1,
        W2, b2, g2, be2, rm2, rv2,
        W3, b3, g3, be3, rm3, rv3,
        fW1, fb1, fW2, fb2, fW3, fb3, fW4, fb4,
        (float*)d_out);
}

// round 5
// speedup vs baseline: 1.8469x; 1.0070x over previous
#include <cuda_runtime.h>
#include <cuda_bf16.h>
#include <cstdint>

#define GRAPHS 4096
#define NPG 18
#define NNODES (GRAPHS * NPG)
#define FIN 1536
#define EPERG 306
#define SLOPE 0.01f
#define BN_EPS 1e-5f

#define NKSTEP (FIN / 16)            // 96 k-steps of 16

// Scratch
__device__ float g_P1[(size_t)NNODES * 32];
// W1 fragments, packed per k-step in exact mma.sync B-fragment order:
// [s][j][lane][4] uint32 ; j=0 -> regs r0..r3, j=1 -> r4..r7
// reg ri: nt = ri>>1, which = ri&1; value = bf16x2(W[k][n], W[k+1][n])
//   n = nt*8 + (lane>>2), k = s*16 + (lane&3)*2 + which*8
__device__ uint32_t g_fragH[NKSTEP * 256];
__device__ uint32_t g_fragL[NKSTEP * 256];

// ---------------------------------------------------------------------------
__device__ __forceinline__ void mma16816(float* c, const uint32_t* a, const uint32_t* b) {
    asm volatile("mma.sync.aligned.m16n8k16.row.col.f32.bf16.bf16.f32 "
        "{%0,%1,%2,%3}, {%4,%5,%6,%7}, {%8,%9}, {%0,%1,%2,%3};"
        : "+f"(c[0]), "+f"(c[1]), "+f"(c[2]), "+f"(c[3])
        : "r"(a[0]), "r"(a[1]), "r"(a[2]), "r"(a[3]), "r"(b[0]), "r"(b[1]));
}
// pack two f32 -> bf16x2 (first arg -> low half)
__device__ __forceinline__ uint32_t pack_bf16x2(float lo, float hi) {
    uint32_t r;
    asm("cvt.rn.bf16x2.f32 %0, %1, %2;" : "=r"(r) : "f"(hi), "f"(lo));
    return r;
}
// split a float2 into hi bf16x2 and lo (residual) bf16x2
__device__ __forceinline__ void split2(float2 v, uint32_t& hi, uint32_t& lo) {
    hi = pack_bf16x2(v.x, v.y);
    float f0 = __uint_as_float(hi << 16);
    float f1 = __uint_as_float(hi & 0xFFFF0000u);
    lo = pack_bf16x2(v.x - f0, v.y - f1);
}

// ---------------------------------------------------------------------------
// Kernel 0: build W1 bf16 hi/lo fragment-packed arrays. 6144 threads.
// ---------------------------------------------------------------------------
__global__ __launch_bounds__(256) void wconv_kernel(const float* __restrict__ W1) {
    int t = blockIdx.x * 256 + threadIdx.x;        // 0..6143
    int s = t >> 6;
    int rem = t & 63;
    int j = rem >> 5, lane = rem & 31;
    uint32_t h[4], l[4];
#pragma unroll
    for (int i = 0; i < 4; i++) {
        int ri = j * 4 + i;
        int nt = ri >> 1, which = ri & 1;
        int n = nt * 8 + (lane >> 2);
        int k = s * 16 + (lane & 3) * 2 + which * 8;
        float x0 = W1[(size_t)k * 32 + n];
        float x1 = W1[(size_t)(k + 1) * 32 + n];
        split2(make_float2(x0, x1), h[i], l[i]);
    }
    int o = s * 256 + j * 128 + lane * 4;
    *(uint4*)(g_fragH + o) = make_uint4(h[0], h[1], h[2], h[3]);
    *(uint4*)(g_fragL + o) = make_uint4(l[0], l[1], l[2], l[3]);
}

// ---------------------------------------------------------------------------
// Kernel 1: P1 = X @ W1. Direct-fragment mma.sync, no smem, no syncthreads.
// CTA: 256 thr (8 warps) x 16 rows/warp = 128 rows; N=32 full.
// ---------------------------------------------------------------------------
__global__ __launch_bounds__(256) void gemm1_mma_kernel(const float* __restrict__ X)
{
    const int tid = threadIdx.x;
    const int wid = tid >> 5;
    const int lane = tid & 31;
    const int row0 = blockIdx.x * 128;
    const int r = row0 + wid * 16 + (lane >> 2);

    const float* xr0 = X + (size_t)r * FIN + (lane & 3) * 2;
    const float* xr1 = xr0 + (size_t)8 * FIN;
    const uint4* fH = (const uint4*)g_fragH + lane;   // + s*64 (+32 for j=1)
    const uint4* fL = (const uint4*)g_fragL + lane;

    float acc[4][4];
#pragma unroll
    for (int nt = 0; nt < 4; nt++)
#pragma unroll
        for (int q = 0; q < 4; q++) acc[nt][q] = 0.f;

#pragma unroll 2
    for (int s = 0; s < NKSTEP; s++) {
        const int k = s * 16;
        float2 a0 = *(const float2*)(xr0 + k);
        float2 a1 = *(const float2*)(xr1 + k);
        float2 a2 = *(const float2*)(xr0 + k + 8);
        float2 a3 = *(const float2*)(xr1 + k + 8);
        uint4 h0 = fH[s * 64];
        uint4 h1 = fH[s * 64 + 32];
        uint4 l0 = fL[s * 64];
        uint4 l1 = fL[s * 64 + 32];

        uint32_t ahi[4], alo[4];
        split2(a0, ahi[0], alo[0]);
        split2(a1, ahi[1], alo[1]);
        split2(a2, ahi[2], alo[2]);
        split2(a3, ahi[3], alo[3]);

        uint32_t bhi[8] = {h0.x, h0.y, h0.z, h0.w, h1.x, h1.y, h1.z, h1.w};
        uint32_t blo[8] = {l0.x, l0.y, l0.z, l0.w, l1.x, l1.y, l1.z, l1.w};

#pragma unroll
        for (int nt = 0; nt < 4; nt++) {
            mma16816(acc[nt], ahi, bhi + nt * 2);
            mma16816(acc[nt], ahi, blo + nt * 2);
            mma16816(acc[nt], alo, bhi + nt * 2);
        }
    }

    // epilogue: fragment -> g_P1
    {
        int cb = (lane & 3) * 2;
#pragma unroll
        for (int nt = 0; nt < 4; nt++) {
            *(float2*)(g_P1 + (size_t)r * 32 + nt * 8 + cb) =
                make_float2(acc[nt][0], acc[nt][1]);
            *(float2*)(g_P1 + (size_t)(r + 8) * 32 + nt * 8 + cb) =
                make_float2(acc[nt][2], acc[nt][3]);
        }
    }
}

// ---------------------------------------------------------------------------
// Kernel 2: per-CTA pipeline for TWO graphs (2048 CTAs, 288 threads).
// Aggregate-then-transform; GEMM3+BN+lrelu+pool fused (h3 never stored);
// W2/W3/fW loads amortized over 2 graphs.
// ---------------------------------------------------------------------------
__device__ __forceinline__ float lrelu(float v) { return v >= 0.f ? v : SLOPE * v; }
__device__ __forceinline__ float4 f4fma(float a, float4 b, float4 c) {
    return make_float4(fmaf(a, b.x, c.x), fmaf(a, b.y, c.y),
                       fmaf(a, b.z, c.z), fmaf(a, b.w, c.w));
}
__device__ __forceinline__ float4 bn_lrelu4(float4 acc, float4 bb, float4 s, float4 t) {
    float4 o;
    o.x = lrelu(fmaf(acc.x + bb.x, s.x, t.x));
    o.y = lrelu(fmaf(acc.y + bb.y, s.y, t.y));
    o.z = lrelu(fmaf(acc.z + bb.z, s.z, t.z));
    o.w = lrelu(fmaf(acc.w + bb.w, s.w, t.w));
    return o;
}

__global__ __launch_bounds__(288, 4) void graph_kernel(
    const float* __restrict__ ew,
    const float* __restrict__ b1, const float* __restrict__ g1,
    const float* __restrict__ be1, const float* __restrict__ rm1, const float* __restrict__ rv1,
    const float* __restrict__ W2, const float* __restrict__ b2, const float* __restrict__ g2,
    const float* __restrict__ be2, const float* __restrict__ rm2, const float* __restrict__ rv2,
    const float* __restrict__ W3, const float* __restrict__ b3, const float* __restrict__ g3,
    const float* __restrict__ be3, const float* __restrict__ rm3, const float* __restrict__ rv3,
    const float* __restrict__ fW1, const float* __restrict__ fb1,
    const float* __restrict__ fW2, const float* __restrict__ fb2,
    const float* __restrict__ fW3, const float* __restrict__ fb3,
    const float* __restrict__ fW4, const float* __restrict__ fb4,
    float* __restrict__ out)
{
    __shared__ __align__(16) float Wm[2][18][20];
    __shared__ __align__(16) float A[2][18][20];
    __shared__ float dinv[2][18];
    __shared__ __align__(16) float bns1[32], bnb1[32];
    __shared__ __align__(16) float bns2[64], bnb2[64];
    __shared__ __align__(16) float bns3[128], bnb3[128];
    __shared__ __align__(16) float bufA[2 * 18 * 64];  // pitch 64
    __shared__ __align__(16) float bufB[2 * 18 * 64];
    __shared__ __align__(16) float part[9][2][128];
    __shared__ __align__(16) float pvec[2][128];
    __shared__ __align__(16) float p2[2][2][64];
    __shared__ float m1[2][64], m2[2][32], m3[2][16];

    const int g0 = blockIdx.x * 2;
    const int tid = threadIdx.x;

    // --- fold BN constants ---
    if (tid < 32) {
        float s = g1[tid] * rsqrtf(rv1[tid] + BN_EPS);
        bns1[tid] = s; bnb1[tid] = be1[tid] - rm1[tid] * s;
    } else if (tid < 96) {
        int f = tid - 32;
        float s = g2[f] * rsqrtf(rv2[f] + BN_EPS);
        bns2[f] = s; bnb2[f] = be2[f] - rm2[f] * s;
    } else if (tid < 224) {
        int f = tid - 96;
        float s = g3[f] * rsqrtf(rv3[f] + BN_EPS);
        bns3[f] = s; bnb3[f] = be3[f] - rm3[f] * s;
    }

    // --- adjacency (2 graphs) ---
    for (int t = tid; t < 648; t += 288) {
        int g = t / 324, rem = t - g * 324;
        int s = rem / 18, d = rem - s * 18;
        Wm[g][s][d] = (s == d) ? 1.0f
                    : ew[(size_t)(g0 + g) * EPERG + s * 17 + d - (d > s ? 1 : 0)];
    }
    // load P1 -> bufA[g][r][0..31]
    {
        int g = tid / 144, rem = tid - g * 144;
        int r = rem >> 3, f4 = rem & 7;
        *(float4*)&bufA[(g * 18 + r) * 64 + f4 * 4] =
            *(const float4*)(g_P1 + ((size_t)(g0 + g) * 18 + r) * 32 + f4 * 4);
    }
    __syncthreads();
    if (tid < 36) {
        int g = tid / 18, c = tid - g * 18;
        float sum = 0.f;
#pragma unroll
        for (int s = 0; s < 18; s++) sum += Wm[g][s][c];
        dinv[g][c] = rsqrtf(sum);
    }
    __syncthreads();
    for (int t = tid; t < 648; t += 288) {
        int g = t / 324, rem = t - g * 324;
        int c = rem / 18, r = rem - c * 18;
        A[g][c][r] = dinv[g][r] * dinv[g][c] * Wm[g][r][c];
    }
    __syncthreads();

    // --- layer1: h1 = lrelu(bn1(A @ P1 + b1)) -> bufB (width 32) ---
    {
        int g = tid / 144, rem = tid - g * 144;
        int c = rem >> 3, f4 = rem & 7;
        float4 acc = make_float4(0.f, 0.f, 0.f, 0.f);
#pragma unroll
        for (int r = 0; r < 18; r++)
            acc = f4fma(A[g][c][r], *(float4*)&bufA[(g * 18 + r) * 64 + f4 * 4], acc);
        float4 o = bn_lrelu4(acc, __ldg((const float4*)b1 + f4),
                             *(float4*)&bns1[f4 * 4], *(float4*)&bnb1[f4 * 4]);
        *(float4*)&bufB[(g * 18 + c) * 64 + f4 * 4] = o;
    }
    __syncthreads();

    // --- layer2 agg-first: g2m = A @ h1 -> bufA (width 32) ---
    {
        int g = tid / 144, rem = tid - g * 144;
        int c = rem >> 3, f4 = rem & 7;
        float4 acc = make_float4(0.f, 0.f, 0.f, 0.f);
#pragma unroll
        for (int r = 0; r < 18; r++)
            acc = f4fma(A[g][c][r], *(float4*)&bufB[(g * 18 + r) * 64 + f4 * 4], acc);
        *(float4*)&bufA[(g * 18 + c) * 64 + f4 * 4] = acc;
    }
    __syncthreads();

    // --- layer2 GEMM: h2 = lrelu(bn2(g2m @ W2 + b2)) -> bufB (width 64),
    //     both graphs per thread (W2 loads shared) ---
    {
        int c = tid >> 4, f4 = tid & 15;   // 18 x 16 = 288
        float4 acc0 = make_float4(0.f, 0.f, 0.f, 0.f);
        float4 acc1 = make_float4(0.f, 0.f, 0.f, 0.f);
#pragma unroll 8
        for (int k = 0; k < 32; k++) {
            float4 w = __ldg((const float4*)(W2 + (size_t)k * 64) + f4);
            acc0 = f4fma(bufA[(0 * 18 + c) * 64 + k], w, acc0);
            acc1 = f4fma(bufA[(1 * 18 + c) * 64 + k], w, acc1);
        }
        float4 bb = __ldg((const float4*)b2 + f4);
        float4 s = *(float4*)&bns2[f4 * 4];
        float4 t = *(float4*)&bnb2[f4 * 4];
        *(float4*)&bufB[(0 * 18 + c) * 64 + f4 * 4] = bn_lrelu4(acc0, bb, s, t);
        *(float4*)&bufB[(1 * 18 + c) * 64 + f4 * 4] = bn_lrelu4(acc1, bb, s, t);
    }
    __syncthreads();

    // --- layer3 agg-first: g3m = A @ h2 -> bufA (width 64) ---
    {
        int c = tid >> 4, f4 = tid & 15;
#pragma unroll
        for (int g = 0; g < 2; g++) {
            float4 acc = make_float4(0.f, 0.f, 0.f, 0.f);
#pragma unroll
            for (int r = 0; r < 18; r++)
                acc = f4fma(A[g][c][r], *(float4*)&bufB[(g * 18 + r) * 64 + f4 * 4], acc);
            *(float4*)&bufA[(g * 18 + c) * 64 + f4 * 4] = acc;
        }
    }
    __syncthreads();

    // --- layer3 GEMM + BN + lrelu + pool partial (fused, h3 never stored) ---
    {
        int cg = tid >> 5, f4 = tid & 31;  // 9 warps x 32 lanes
        int ra = cg * 2, rb = ra + 1;
        float4 a00 = make_float4(0.f, 0.f, 0.f, 0.f), a01 = a00, a10 = a00, a11 = a00;
#pragma unroll 8
        for (int k = 0; k < 64; k++) {
            float4 w = __ldg((const float4*)(W3 + (size_t)k * 128) + f4);
            a00 = f4fma(bufA[(0 * 18 + ra) * 64 + k], w, a00);
            a01 = f4fma(bufA[(0 * 18 + rb) * 64 + k], w, a01);
            a10 = f4fma(bufA[(1 * 18 + ra) * 64 + k], w, a10);
            a11 = f4fma(bufA[(1 * 18 + rb) * 64 + k], w, a11);
        }
        float4 bb = __ldg((const float4*)b3 + f4);
        float4 s = *(float4*)&bns3[f4 * 4];
        float4 t = *(float4*)&bnb3[f4 * 4];
        float4 o00 = bn_lrelu4(a00, bb, s, t);
        float4 o01 = bn_lrelu4(a01, bb, s, t);
        float4 o10 = bn_lrelu4(a10, bb, s, t);
        float4 o11 = bn_lrelu4(a11, bb, s, t);
        *(float4*)&part[cg][0][f4 * 4] =
            make_float4(o00.x + o01.x, o00.y + o01.y, o00.z + o01.z, o00.w + o01.w);
        *(float4*)&part[cg][1][f4 * 4] =
            make_float4(o10.x + o11.x, o10.y + o11.y, o10.z + o11.z, o10.w + o11.w);
    }
    __syncthreads();

    // --- pool reduce: pvec[g][f] = sum_cg part / 18 ---
    if (tid < 256) {
        int g = tid >> 7, f = tid & 127;
        float s = 0.f;
#pragma unroll
        for (int cg = 0; cg < 9; cg++) s += part[cg][g][f];
        pvec[g][f] = s * (1.0f / 18.0f);
    }
    __syncthreads();

    // --- MLP head ---
    if (tid < 256) {   // fW1: 2g x 64f x 2 ksplit
        int g = tid >> 7, rem = tid & 127;
        int ks = rem >> 6, f = rem & 63;
        float acc = 0.f;
#pragma unroll
        for (int k = ks * 64; k < ks * 64 + 64; k++)
            acc = fmaf(pvec[g][k], __ldg(fW1 + (size_t)k * 64 + f), acc);
        p2[g][ks][f] = acc;
    }
    __syncthreads();
    if (tid < 128) {
        int g = tid >> 6, f = tid & 63;
        m1[g][f] = lrelu(p2[g][0][f] + p2[g][1][f] + __ldg(fb1 + f));
    }
    __syncthreads();
    if (tid < 64) {
        int g = tid >> 5, f = tid & 31;
        float acc = __ldg(fb2 + f);
#pragma unroll
        for (int k = 0; k < 64; k++)
            acc = fmaf(m1[g][k], __ldg(fW2 + (size_t)k * 32 + f), acc);
        m2[g][f] = lrelu(acc);
    }
    __syncthreads();
    if (tid < 32) {
        int g = tid >> 4, f = tid & 15;
        float acc = __ldg(fb3 + f);
#pragma unroll
        for (int k = 0; k < 32; k++)
            acc = fmaf(m2[g][k], __ldg(fW3 + (size_t)k * 16 + f), acc);
        m3[g][f] = lrelu(acc);
    }
    __syncthreads();
    {
        int wid = tid >> 5, lane = tid & 31;
        if (wid < 2) {
            float p = (lane < 16) ? m3[wid][lane] * __ldg(fW4 + lane) : 0.f;
#pragma unroll
            for (int off = 8; off > 0; off >>= 1)
                p += __shfl_down_sync(0xFFFFFFFFu, p, off);
            if (lane == 0) out[g0 + wid] = p + __ldg(fb4);
        }
    }
}

// ---------------------------------------------------------------------------
extern "C" void kernel_launch(void* const* d_in, const int* in_sizes, int n_in,
                              void* d_out, int out_size)
{
    (void)in_sizes; (void)n_in; (void)out_size;
    const float* x   = (const float*)d_in[0];
    const float* ew  = (const float*)d_in[2];
    const float* W1  = (const float*)d_in[4];
    const float* b1  = (const float*)d_in[5];
    const float* g1  = (const float*)d_in[6];
    const float* be1 = (const float*)d_in[7];
    const float* rm1 = (const float*)d_in[8];
    const float* rv1 = (const float*)d_in[9];
    const float* W2  = (const float*)d_in[10];
    const float* b2  = (const float*)d_in[11];
    const float* g2  = (const float*)d_in[12];
    const float* be2 = (const float*)d_in[13];
    const float* rm2 = (const float*)d_in[14];
    const float* rv2 = (const float*)d_in[15];
    const float* W3  = (const float*)d_in[16];
    const float* b3  = (const float*)d_in[17];
    const float* g3  = (const float*)d_in[18];
    const float* be3 = (const float*)d_in[19];
    const float* rm3 = (const float*)d_in[20];
    const float* rv3 = (const float*)d_in[21];
    const float* fW1 = (const float*)d_in[22];
    const float* fb1 = (const float*)d_in[23];
    const float* fW2 = (const float*)d_in[24];
    const float* fb2 = (const float*)d_in[25];
    const float* fW3 = (const float*)d_in[26];
    const float* fb3 = (const float*)d_in[27];
    const float* fW4 = (const float*)d_in[28];
    const float* fb4 = (const float*)d_in[29];

    wconv_kernel<<<24, 256>>>(W1);
    gemm1_mma_kernel<<<NNODES / 128, 256>>>(x);
    graph_kernel<<<GRAPHS / 2, 288>>>(ew,
        b1, g1, be1, rm1, rv1,
        W2, b2, g2, be2, rm2, rv2,
        W3, b3, g3, be3, rm3, rv3,
        fW1, fb1, fW2, fb2, fW3, fb3, fW4, fb4,
        (float*)d_out);
}